// round 16
// baseline (speedup 1.0000x reference)
#include <cuda_runtime.h>
#include <cuda_bf16.h>
#include <cstdint>

// Problem constants (B=2, S=2048, NX=1024, H=16, D=64)
#define BB 2
#define SS 2048
#define NXC 1024
#define HH 16
#define DD 64
#define MTOK (BB*SS)   // 4096

// Scratch (device globals — referenced ONLY inside device code; passing them
// as kernel args from host was the R12 bug). All tf32-rounded f32.
__device__ float g_q[(size_t)BB*HH*SS*DD];    // [B,H,S,D]
__device__ float g_k[(size_t)BB*HH*SS*DD];    // [B,H,D,S] (transposed)
__device__ float g_v[(size_t)BB*HH*SS*DD];    // [B,H,S,D]
__device__ float g_a[(size_t)BB*SS*NXC];      // attn out
__device__ float g_xtf[(size_t)MTOK*NXC];     // x
__device__ float g_w1[(size_t)NXC*3*NXC];     // w_attn
__device__ float g_w2[(size_t)NXC*NXC];       // w_proj

// ---------------------------------------------------------------------------
// helpers
// ---------------------------------------------------------------------------
static __device__ __forceinline__ uint32_t f2tf(float f) {
    uint32_t r;
    asm("cvt.rna.tf32.f32 %0, %1;" : "=r"(r) : "f"(f));
    return r;
}
static __device__ __forceinline__ void mma1688(float* c, const uint32_t* a,
                                               const uint32_t* b) {
    asm volatile(
        "mma.sync.aligned.m16n8k8.row.col.f32.tf32.tf32.f32 "
        "{%0,%1,%2,%3}, {%4,%5,%6,%7}, {%8,%9}, {%0,%1,%2,%3};"
        : "+f"(c[0]), "+f"(c[1]), "+f"(c[2]), "+f"(c[3])
        : "r"(a[0]), "r"(a[1]), "r"(a[2]), "r"(a[3]),
          "r"(b[0]), "r"(b[1]));
}

// ---------------------------------------------------------------------------
// Elementwise f32 -> tf32-rounded f32 copy. dst: 0=g_xtf 1=g_w1 2=g_w2.
// ---------------------------------------------------------------------------
__global__ void cvt_tf32_kernel(const float* __restrict__ in, int dst)
{
    float* out = (dst == 0) ? g_xtf : (dst == 1) ? g_w1 : g_w2;
    const int i = (blockIdx.x * 256 + threadIdx.x) * 4;
    float4 v = *(const float4*)(in + i);
    *(uint4*)(out + i) =
        make_uint4(f2tf(v.x), f2tf(v.y), f2tf(v.z), f2tf(v.w));
}

// ---------------------------------------------------------------------------
// tf32 tensor-core GEMM, k-pair permuted smem + all-LDS64 fragment feed.
// Block tile 128x128, 8 warps as 2(warp_m) x 4(warp_n), warp tile 64x32.
// Per ks-step: 8 A-LDS64 + 4 B-LDS64 feed 16 MMAs (was 24 LDS32 : 16 MMA).
// SMEM permutation within each 32-deep K chunk: pos(k) maps the MMA pair
// (k, k+4) to adjacent words:  pos = (k>>3)*8 + (k&3)*2 + ((k>>2)&1).
//   A:  As[r][pos(k)]            row stride 40 words (conflict-free LDS64)
//   B:  Bs[g=(k>>3)*4+(k&3)][n*2+h] group stride 264 (conflict-free LDS64)
// mode 1 (QKV):  A=g_xtf, B=g_w1, scatter rounded q/v [B,H,S,D], k [B,H,D,S]
// mode 0 (proj): A=g_a,   B=g_w2, C = acc + bias
// ---------------------------------------------------------------------------
#define ASTR2 40
#define BGRP 264

__global__ __launch_bounds__(256)
void tc_gemm(const float* __restrict__ bias, float* __restrict__ C,
             int K, int N, int mode)
{
    __shared__ uint32_t As[128 * ASTR2];   // 20.0 KB
    __shared__ uint32_t Bs[16 * BGRP];     // 16.5 KB

    const int tid = threadIdx.x;
    const int lane = tid & 31;
    const int warp = tid >> 5;
    const int warp_m = warp >> 2;          // 0..1  (64 rows each)
    const int warp_n = warp & 3;           // 0..3  (32 cols each)
    const int row0 = blockIdx.y * 128;
    const int col0 = blockIdx.x * 128;
    const float* Ap = mode ? g_xtf : g_a;
    const float* Bm = mode ? g_w1 : g_w2;

    float acc[4][4][4];
#pragma unroll
    for (int mi = 0; mi < 4; mi++)
#pragma unroll
        for (int ni = 0; ni < 4; ni++)
#pragma unroll
            for (int e = 0; e < 4; e++) acc[mi][ni][e] = 0.f;

    const int lr = lane >> 2;   // 0..7
    const int lc = lane & 3;    // 0..3

    for (int k0 = 0; k0 < K; k0 += 32) {
        // --- Stage A tile 128x32 with pair-permuted columns ---
#pragma unroll
        for (int t = 0; t < 4; t++) {
            const int fid = tid + t * 256;        // 0..1023
            const int r = fid >> 3;               // 0..127
            const int c4 = (fid & 7) << 2;        // 0,4,...,28
            float4 v = *(const float4*)(Ap + (size_t)(row0 + r) * K + k0 + c4);
            // pos(c4+i) = (c4>>3)*8 + ((c4&4)>>2) + 2*i
            const int off = r * ASTR2 + ((c4 >> 3) << 3) + ((c4 & 4) >> 2);
            As[off + 0] = __float_as_uint(v.x);
            As[off + 2] = __float_as_uint(v.y);
            As[off + 4] = __float_as_uint(v.z);
            As[off + 6] = __float_as_uint(v.w);
        }
        // --- Stage B tile 32x128: group g=(k>>3)*4+(k&3), word n*2+h ---
#pragma unroll
        for (int t = 0; t < 4; t++) {
            const int fid = tid + t * 256;
            const int kk = fid >> 5;              // 0..31
            const int n4 = (fid & 31) << 2;       // 0..124
            float4 v = *(const float4*)(Bm + (size_t)(k0 + kk) * N + col0 + n4);
            const int g = ((kk >> 3) << 2) + (kk & 3);
            const int h = (kk >> 2) & 1;
            const int off = g * BGRP + n4 * 2 + h;
            Bs[off + 0] = __float_as_uint(v.x);
            Bs[off + 2] = __float_as_uint(v.y);
            Bs[off + 4] = __float_as_uint(v.z);
            Bs[off + 6] = __float_as_uint(v.w);
        }
        __syncthreads();

#pragma unroll
        for (int ks = 0; ks < 4; ks++) {
            const int cc = ks * 8 + lc * 2;       // permuted col of (k, k+4)
            uint32_t af[4][4];
#pragma unroll
            for (int mi = 0; mi < 4; mi++) {
                const int r = warp_m * 64 + mi * 16 + lr;
                uint2 p0 = *(const uint2*)&As[r * ASTR2 + cc];
                uint2 p1 = *(const uint2*)&As[(r + 8) * ASTR2 + cc];
                af[mi][0] = p0.x; af[mi][2] = p0.y;
                af[mi][1] = p1.x; af[mi][3] = p1.y;
            }
            const int g = ks * 4 + lc;
            uint32_t bf[4][2];
#pragma unroll
            for (int ni = 0; ni < 4; ni++) {
                const int n = warp_n * 32 + ni * 8 + lr;
                uint2 q = *(const uint2*)&Bs[g * BGRP + n * 2];
                bf[ni][0] = q.x; bf[ni][1] = q.y;
            }
#pragma unroll
            for (int mi = 0; mi < 4; mi++)
#pragma unroll
                for (int ni = 0; ni < 4; ni++)
                    mma1688(acc[mi][ni], af[mi], bf[ni]);
        }
        __syncthreads();
    }

    // Epilogue
#pragma unroll
    for (int mi = 0; mi < 4; mi++) {
#pragma unroll
        for (int ni = 0; ni < 4; ni++) {
            const int r = row0 + warp_m * 64 + mi * 16 + lr;
            const int c = col0 + warp_n * 32 + ni * 8 + 2 * lc;
#pragma unroll
            for (int e = 0; e < 4; e++) {
                const int row = r + (e >> 1) * 8;
                const int col = c + (e & 1);
                const float val = acc[mi][ni][e] + bias[col];
                if (mode == 0) {
                    C[(size_t)row * NXC + col] = val;
                } else {
                    const float rv = __uint_as_float(f2tf(val));
                    const int bidx = row >> 11;
                    const int s = row & 2047;
                    const int which = col >> 10;
                    const int hd = col & 1023;
                    const int h = hd >> 6;
                    const int d = hd & 63;
                    if (which == 0) {
                        g_q[(((size_t)(bidx * HH + h)) * SS + s) * DD + d] = rv;
                    } else if (which == 1) {
                        g_k[(((size_t)(bidx * HH + h)) * DD + d) * SS + s] = rv;
                    } else {
                        g_v[(((size_t)(bidx * HH + h)) * SS + s) * DD + d] = rv;
                    }
                }
            }
        }
    }
}

// ---------------------------------------------------------------------------
// Tensor-core flash attention — UNCHANGED from R13 (passing, 2 CTAs/SM,
// heavy-first scheduling, raw uint4 staging of pre-rounded tf32 data).
// ---------------------------------------------------------------------------
#define QSTR 68
#define KSTR 72
#define ATTN_SMEM ((2*128*QSTR + 2*64*KSTR) * 4)   // 106496 bytes

__global__ __launch_bounds__(256)
void attn_mma_kernel()
{
    extern __shared__ uint32_t smem[];
    uint32_t* Qs = smem;                      // 128*68 tf32
    uint32_t* Ps = Qs + 128 * QSTR;           // 128*68 tf32
    uint32_t* Ks = Ps + 128 * QSTR;           // 64*72 tf32 [d][key]
    uint32_t* Vs = Ks + 64 * KSTR;            // 64*72 tf32 [c][d]

    const int bh = blockIdx.x;
    const int qt = (gridDim.y - 1) - blockIdx.y;   // heavy tiles first
    const int q0 = qt * 128;
    const int tid = threadIdx.x;
    const int lane = tid & 31;
    const int warp = tid >> 5;
    const int lr = lane >> 2;
    const int lc = lane & 3;
    const int wr = warp * 16;

    const float* Qg  = g_q + (size_t)bh * SS * DD;    // [s][d]
    const float* KgT = g_k + (size_t)bh * DD * SS;    // [d][s]
    const float* Vg  = g_v + (size_t)bh * SS * DD;    // [s][d]

#pragma unroll
    for (int t = 0; t < 8; t++) {
        const int fid = tid + t * 256;
        const int r = fid >> 4;
        const int c4 = (fid & 15) << 2;
        *(uint4*)&Qs[r * QSTR + c4] =
            *(const uint4*)(Qg + (size_t)(q0 + r) * DD + c4);
    }

    float oacc[8][4];
#pragma unroll
    for (int ni = 0; ni < 8; ni++)
#pragma unroll
        for (int e = 0; e < 4; e++) oacc[ni][e] = 0.f;
    float m0 = -1e30f, m1 = -1e30f, l0 = 0.f, l1 = 0.f;
    const float scale = 0.125f;

    const int nkt = 2 * qt + 2;
    for (int kt = 0; kt < nkt; kt++) {
        const int k0 = kt * 64;

        __syncthreads();
#pragma unroll
        for (int t = 0; t < 4; t++) {
            const int fid = tid + t * 256;
            const int r = fid >> 4;
            const int c4 = (fid & 15) << 2;
            *(uint4*)&Ks[r * KSTR + c4] =
                *(const uint4*)(KgT + (size_t)r * SS + k0 + c4);
            *(uint4*)&Vs[r * KSTR + c4] =
                *(const uint4*)(Vg + (size_t)(k0 + r) * DD + c4);
        }
        __syncthreads();

        float sacc[8][4];
#pragma unroll
        for (int ni = 0; ni < 8; ni++)
#pragma unroll
            for (int e = 0; e < 4; e++) sacc[ni][e] = 0.f;
#pragma unroll
        for (int ks = 0; ks < 8; ks++) {
            uint32_t af[4];
            const int c = ks * 8 + lc;
            af[0] = Qs[(wr + lr) * QSTR + c];
            af[1] = Qs[(wr + lr + 8) * QSTR + c];
            af[2] = Qs[(wr + lr) * QSTR + c + 4];
            af[3] = Qs[(wr + lr + 8) * QSTR + c + 4];
#pragma unroll
            for (int ni = 0; ni < 8; ni++) {
                uint32_t bf[2];
                const int n = ni * 8 + lr;
                bf[0] = Ks[c * KSTR + n];
                bf[1] = Ks[(c + 4) * KSTR + n];
                mma1688(sacc[ni], af, bf);
            }
        }

        const bool need_mask = (k0 + 63 > q0);
        const int r0g = q0 + wr + lr;
        const int r1g = r0g + 8;
#pragma unroll
        for (int ni = 0; ni < 8; ni++) {
            const int c0g = k0 + ni * 8 + 2 * lc;
#pragma unroll
            for (int e = 0; e < 4; e++) sacc[ni][e] *= scale;
            if (need_mask) {
                if (c0g     > r0g) sacc[ni][0] = -1e30f;
                if (c0g + 1 > r0g) sacc[ni][1] = -1e30f;
                if (c0g     > r1g) sacc[ni][2] = -1e30f;
                if (c0g + 1 > r1g) sacc[ni][3] = -1e30f;
            }
        }

        float mx0 = -1e30f, mx1 = -1e30f;
#pragma unroll
        for (int ni = 0; ni < 8; ni++) {
            mx0 = fmaxf(mx0, fmaxf(sacc[ni][0], sacc[ni][1]));
            mx1 = fmaxf(mx1, fmaxf(sacc[ni][2], sacc[ni][3]));
        }
        mx0 = fmaxf(mx0, __shfl_xor_sync(0xffffffffu, mx0, 1));
        mx0 = fmaxf(mx0, __shfl_xor_sync(0xffffffffu, mx0, 2));
        mx1 = fmaxf(mx1, __shfl_xor_sync(0xffffffffu, mx1, 1));
        mx1 = fmaxf(mx1, __shfl_xor_sync(0xffffffffu, mx1, 2));

        const float mn0 = fmaxf(m0, mx0);
        const float mn1 = fmaxf(m1, mx1);
        const float a0 = __expf(m0 - mn0);
        const float a1 = __expf(m1 - mn1);
        m0 = mn0; m1 = mn1;

        float sum0 = 0.f, sum1 = 0.f;
#pragma unroll
        for (int ni = 0; ni < 8; ni++) {
            const float p0 = __expf(sacc[ni][0] - mn0);
            const float p1 = __expf(sacc[ni][1] - mn0);
            const float p2 = __expf(sacc[ni][2] - mn1);
            const float p3 = __expf(sacc[ni][3] - mn1);
            sum0 += p0 + p1;
            sum1 += p2 + p3;
            const int co = ni * 8 + 2 * lc;
            *(uint2*)&Ps[(wr + lr) * QSTR + co]     = make_uint2(f2tf(p0), f2tf(p1));
            *(uint2*)&Ps[(wr + lr + 8) * QSTR + co] = make_uint2(f2tf(p2), f2tf(p3));
        }
        sum0 += __shfl_xor_sync(0xffffffffu, sum0, 1);
        sum0 += __shfl_xor_sync(0xffffffffu, sum0, 2);
        sum1 += __shfl_xor_sync(0xffffffffu, sum1, 1);
        sum1 += __shfl_xor_sync(0xffffffffu, sum1, 2);
        l0 = l0 * a0 + sum0;
        l1 = l1 * a1 + sum1;

#pragma unroll
        for (int ni = 0; ni < 8; ni++) {
            oacc[ni][0] *= a0; oacc[ni][1] *= a0;
            oacc[ni][2] *= a1; oacc[ni][3] *= a1;
        }
        __syncwarp();

#pragma unroll
        for (int ks = 0; ks < 8; ks++) {
            uint32_t af[4];
            const int c = ks * 8 + lc;
            af[0] = Ps[(wr + lr) * QSTR + c];
            af[1] = Ps[(wr + lr + 8) * QSTR + c];
            af[2] = Ps[(wr + lr) * QSTR + c + 4];
            af[3] = Ps[(wr + lr + 8) * QSTR + c + 4];
#pragma unroll
            for (int ni = 0; ni < 8; ni++) {
                uint32_t bf[2];
                const int n = ni * 8 + lr;
                bf[0] = Vs[c * KSTR + n];
                bf[1] = Vs[(c + 4) * KSTR + n];
                mma1688(oacc[ni], af, bf);
            }
        }
    }

    const int b = bh >> 4;
    const int h = bh & 15;
    const float inv0 = 1.f / l0;
    const float inv1 = 1.f / l1;
    const int r0g = q0 + wr + lr;
#pragma unroll
    for (int ni = 0; ni < 8; ni++) {
        const int col = h * DD + ni * 8 + 2 * lc;
        float* d0 = g_a + ((size_t)(b * SS + r0g)) * NXC + col;
        float* d1 = g_a + ((size_t)(b * SS + r0g + 8)) * NXC + col;
        *(uint2*)d0 = make_uint2(f2tf(oacc[ni][0] * inv0),
                                 f2tf(oacc[ni][1] * inv0));
        *(uint2*)d1 = make_uint2(f2tf(oacc[ni][2] * inv1),
                                 f2tf(oacc[ni][3] * inv1));
    }
}

// ---------------------------------------------------------------------------
extern "C" void kernel_launch(void* const* d_in, const int* in_sizes, int n_in,
                              void* d_out, int out_size)
{
    const float* x      = (const float*)d_in[0];
    const float* w_attn = (const float*)d_in[1];
    const float* b_attn = (const float*)d_in[2];
    const float* w_proj = (const float*)d_in[3];
    const float* b_proj = (const float*)d_in[4];
    float* out = (float*)d_out;

    cudaFuncSetAttribute(attn_mma_kernel,
                         cudaFuncAttributeMaxDynamicSharedMemorySize, ATTN_SMEM);

    // 0) Pre-round operands to tf32 in gmem (dst selected inside kernel)
    cvt_tf32_kernel<<<(MTOK * NXC) / 1024, 256>>>(x, 0);
    cvt_tf32_kernel<<<(NXC * 3 * NXC) / 1024, 256>>>(w_attn, 1);
    cvt_tf32_kernel<<<(NXC * NXC) / 1024, 256>>>(w_proj, 2);

    // 1) QKV GEMM (LDS64 pair feed); K written transposed [B,H,D,S]
    tc_gemm<<<dim3(24, 32), 256>>>(b_attn, nullptr, NXC, 3 * NXC, 1);

    // 2) Tensor-core causal flash attention
    attn_mma_kernel<<<dim3(BB * HH, SS / 128), 256, ATTN_SMEM>>>();

    // 3) Projection (LDS64 pair feed)
    tc_gemm<<<dim3(8, 32), 256>>>(b_proj, out, NXC, NXC, 0);
}

// round 17
// speedup vs baseline: 1.2600x; 1.2600x over previous
#include <cuda_runtime.h>
#include <cuda_bf16.h>
#include <cstdint>

// Problem constants (B=2, S=2048, NX=1024, H=16, D=64)
#define BB 2
#define SS 2048
#define NXC 1024
#define HH 16
#define DD 64
#define MTOK (BB*SS)   // 4096

// Scratch (device globals — referenced ONLY inside device code; passing them
// as kernel args from host was the R12 bug). All tf32-rounded f32.
__device__ float g_q[(size_t)BB*HH*SS*DD];    // [B,H,S,D]
__device__ float g_k[(size_t)BB*HH*SS*DD];    // [B,H,D,S] (transposed)
__device__ float g_v[(size_t)BB*HH*SS*DD];    // [B,H,S,D]
__device__ float g_a[(size_t)BB*SS*NXC];      // attn out
__device__ float g_xtf[(size_t)MTOK*NXC];     // x
__device__ float g_w1[(size_t)NXC*3*NXC];     // w_attn
__device__ float g_w2[(size_t)NXC*NXC];       // w_proj

// ---------------------------------------------------------------------------
// helpers
// ---------------------------------------------------------------------------
static __device__ __forceinline__ uint32_t f2tf(float f) {
    uint32_t r;
    asm("cvt.rna.tf32.f32 %0, %1;" : "=r"(r) : "f"(f));
    return r;
}
static __device__ __forceinline__ void mma1688(float* c, const uint32_t* a,
                                               const uint32_t* b) {
    asm volatile(
        "mma.sync.aligned.m16n8k8.row.col.f32.tf32.tf32.f32 "
        "{%0,%1,%2,%3}, {%4,%5,%6,%7}, {%8,%9}, {%0,%1,%2,%3};"
        : "+f"(c[0]), "+f"(c[1]), "+f"(c[2]), "+f"(c[3])
        : "r"(a[0]), "r"(a[1]), "r"(a[2]), "r"(a[3]),
          "r"(b[0]), "r"(b[1]));
}

// ---------------------------------------------------------------------------
// Elementwise f32 -> tf32-rounded f32 copy. dst: 0=g_xtf 1=g_w1 2=g_w2.
// ---------------------------------------------------------------------------
__global__ void cvt_tf32_kernel(const float* __restrict__ in, int dst)
{
    float* out = (dst == 0) ? g_xtf : (dst == 1) ? g_w1 : g_w2;
    const int i = (blockIdx.x * 256 + threadIdx.x) * 4;
    float4 v = *(const float4*)(in + i);
    *(uint4*)(out + i) =
        make_uint4(f2tf(v.x), f2tf(v.y), f2tf(v.z), f2tf(v.w));
}

// ---------------------------------------------------------------------------
// tf32 tensor-core GEMM, occupancy-optimized: block tile 128x64, 8 warps as
// 4(warp_m) x 2(warp_n), warp tile 32x32 (acc = 32 regs/thread), targeting
// 3 CTAs/SM (24 warps/SM = 6 per SMSP) to cover LDS->MMA latency.
// Feed addressing identical pattern to the proven R13 kernel:
//   A  [m][k] stride 36: bank (4*lr+lc)  — 32 distinct, conflict-free
//   B  [k][n] stride 72: bank (8*lc+lr)  — 32 distinct, conflict-free
// Operands pre-rounded tf32 in gmem; staging is raw uint4; zero cvts.
// mode 1 (QKV):  A=g_xtf, B=g_w1, scatter rounded q/v [B,H,S,D], k [B,H,D,S]
// mode 0 (proj): A=g_a,   B=g_w2, C = acc + bias
// ---------------------------------------------------------------------------
#define ASTR 36
#define BSTR3 72

__global__ __launch_bounds__(256, 3)
void tc_gemm(const float* __restrict__ bias, float* __restrict__ C,
             int K, int N, int mode)
{
    __shared__ uint32_t As[128 * ASTR];   // 18.4 KB
    __shared__ uint32_t Bs[32 * BSTR3];   //  9.2 KB

    const int tid = threadIdx.x;
    const int lane = tid & 31;
    const int warp = tid >> 5;
    const int warp_m = warp >> 1;          // 0..3  (32 rows each)
    const int warp_n = warp & 1;           // 0..1  (32 cols each)
    const int row0 = blockIdx.y * 128;
    const int col0 = blockIdx.x * 64;
    const float* Ap = mode ? g_xtf : g_a;
    const float* Bm = mode ? g_w1 : g_w2;

    float acc[2][4][4];
#pragma unroll
    for (int mi = 0; mi < 2; mi++)
#pragma unroll
        for (int ni = 0; ni < 4; ni++)
#pragma unroll
            for (int e = 0; e < 4; e++) acc[mi][ni][e] = 0.f;

    const int lr = lane >> 2;   // 0..7
    const int lc = lane & 3;    // 0..3

    for (int k0 = 0; k0 < K; k0 += 32) {
        // Stage A tile 128x32 (raw, pre-rounded): 4 x uint4 per thread
#pragma unroll
        for (int t = 0; t < 4; t++) {
            const int fid = tid + t * 256;        // 0..1023
            const int r = fid >> 3;               // 0..127
            const int c4 = (fid & 7) << 2;        // 0,4,...,28
            *(uint4*)&As[r * ASTR + c4] =
                *(const uint4*)(Ap + (size_t)(row0 + r) * K + k0 + c4);
        }
        // Stage B tile 32x64: 2 x uint4 per thread
#pragma unroll
        for (int t = 0; t < 2; t++) {
            const int fid = tid + t * 256;        // 0..511
            const int kk = fid >> 4;              // 0..31
            const int n4 = (fid & 15) << 2;       // 0..60
            *(uint4*)&Bs[kk * BSTR3 + n4] =
                *(const uint4*)(Bm + (size_t)(k0 + kk) * N + col0 + n4);
        }
        __syncthreads();

#pragma unroll
        for (int ks = 0; ks < 4; ks++) {
            const int c = ks * 8 + lc;
            uint32_t af[2][4];
#pragma unroll
            for (int mi = 0; mi < 2; mi++) {
                const int r = warp_m * 32 + mi * 16 + lr;
                af[mi][0] = As[r * ASTR + c];
                af[mi][1] = As[(r + 8) * ASTR + c];
                af[mi][2] = As[r * ASTR + c + 4];
                af[mi][3] = As[(r + 8) * ASTR + c + 4];
            }
            uint32_t bf[4][2];
#pragma unroll
            for (int ni = 0; ni < 4; ni++) {
                const int n = warp_n * 32 + ni * 8 + lr;
                bf[ni][0] = Bs[c * BSTR3 + n];
                bf[ni][1] = Bs[(c + 4) * BSTR3 + n];
            }
#pragma unroll
            for (int mi = 0; mi < 2; mi++)
#pragma unroll
                for (int ni = 0; ni < 4; ni++)
                    mma1688(acc[mi][ni], af[mi], bf[ni]);
        }
        __syncthreads();
    }

    // Epilogue
#pragma unroll
    for (int mi = 0; mi < 2; mi++) {
#pragma unroll
        for (int ni = 0; ni < 4; ni++) {
            const int r = row0 + warp_m * 32 + mi * 16 + lr;
            const int c = col0 + warp_n * 32 + ni * 8 + 2 * lc;
#pragma unroll
            for (int e = 0; e < 4; e++) {
                const int row = r + (e >> 1) * 8;
                const int col = c + (e & 1);
                const float val = acc[mi][ni][e] + bias[col];
                if (mode == 0) {
                    C[(size_t)row * NXC + col] = val;
                } else {
                    const float rv = __uint_as_float(f2tf(val));
                    const int bidx = row >> 11;
                    const int s = row & 2047;
                    const int which = col >> 10;
                    const int hd = col & 1023;
                    const int h = hd >> 6;
                    const int d = hd & 63;
                    if (which == 0) {
                        g_q[(((size_t)(bidx * HH + h)) * SS + s) * DD + d] = rv;
                    } else if (which == 1) {
                        g_k[(((size_t)(bidx * HH + h)) * DD + d) * SS + s] = rv;
                    } else {
                        g_v[(((size_t)(bidx * HH + h)) * SS + s) * DD + d] = rv;
                    }
                }
            }
        }
    }
}

// ---------------------------------------------------------------------------
// Tensor-core flash attention — UNCHANGED (passing at R13/R16: 2 CTAs/SM,
// heavy-first scheduling, raw uint4 staging of pre-rounded tf32 data).
// ---------------------------------------------------------------------------
#define QSTR 68
#define KSTR 72
#define ATTN_SMEM ((2*128*QSTR + 2*64*KSTR) * 4)   // 106496 bytes

__global__ __launch_bounds__(256)
void attn_mma_kernel()
{
    extern __shared__ uint32_t smem[];
    uint32_t* Qs = smem;                      // 128*68 tf32
    uint32_t* Ps = Qs + 128 * QSTR;           // 128*68 tf32
    uint32_t* Ks = Ps + 128 * QSTR;           // 64*72 tf32 [d][key]
    uint32_t* Vs = Ks + 64 * KSTR;            // 64*72 tf32 [c][d]

    const int bh = blockIdx.x;
    const int qt = (gridDim.y - 1) - blockIdx.y;   // heavy tiles first
    const int q0 = qt * 128;
    const int tid = threadIdx.x;
    const int lane = tid & 31;
    const int warp = tid >> 5;
    const int lr = lane >> 2;
    const int lc = lane & 3;
    const int wr = warp * 16;

    const float* Qg  = g_q + (size_t)bh * SS * DD;    // [s][d]
    const float* KgT = g_k + (size_t)bh * DD * SS;    // [d][s]
    const float* Vg  = g_v + (size_t)bh * SS * DD;    // [s][d]

#pragma unroll
    for (int t = 0; t < 8; t++) {
        const int fid = tid + t * 256;
        const int r = fid >> 4;
        const int c4 = (fid & 15) << 2;
        *(uint4*)&Qs[r * QSTR + c4] =
            *(const uint4*)(Qg + (size_t)(q0 + r) * DD + c4);
    }

    float oacc[8][4];
#pragma unroll
    for (int ni = 0; ni < 8; ni++)
#pragma unroll
        for (int e = 0; e < 4; e++) oacc[ni][e] = 0.f;
    float m0 = -1e30f, m1 = -1e30f, l0 = 0.f, l1 = 0.f;
    const float scale = 0.125f;

    const int nkt = 2 * qt + 2;
    for (int kt = 0; kt < nkt; kt++) {
        const int k0 = kt * 64;

        __syncthreads();
#pragma unroll
        for (int t = 0; t < 4; t++) {
            const int fid = tid + t * 256;
            const int r = fid >> 4;
            const int c4 = (fid & 15) << 2;
            *(uint4*)&Ks[r * KSTR + c4] =
                *(const uint4*)(KgT + (size_t)r * SS + k0 + c4);
            *(uint4*)&Vs[r * KSTR + c4] =
                *(const uint4*)(Vg + (size_t)(k0 + r) * DD + c4);
        }
        __syncthreads();

        float sacc[8][4];
#pragma unroll
        for (int ni = 0; ni < 8; ni++)
#pragma unroll
            for (int e = 0; e < 4; e++) sacc[ni][e] = 0.f;
#pragma unroll
        for (int ks = 0; ks < 8; ks++) {
            uint32_t af[4];
            const int c = ks * 8 + lc;
            af[0] = Qs[(wr + lr) * QSTR + c];
            af[1] = Qs[(wr + lr + 8) * QSTR + c];
            af[2] = Qs[(wr + lr) * QSTR + c + 4];
            af[3] = Qs[(wr + lr + 8) * QSTR + c + 4];
#pragma unroll
            for (int ni = 0; ni < 8; ni++) {
                uint32_t bf[2];
                const int n = ni * 8 + lr;
                bf[0] = Ks[c * KSTR + n];
                bf[1] = Ks[(c + 4) * KSTR + n];
                mma1688(sacc[ni], af, bf);
            }
        }

        const bool need_mask = (k0 + 63 > q0);
        const int r0g = q0 + wr + lr;
        const int r1g = r0g + 8;
#pragma unroll
        for (int ni = 0; ni < 8; ni++) {
            const int c0g = k0 + ni * 8 + 2 * lc;
#pragma unroll
            for (int e = 0; e < 4; e++) sacc[ni][e] *= scale;
            if (need_mask) {
                if (c0g     > r0g) sacc[ni][0] = -1e30f;
                if (c0g + 1 > r0g) sacc[ni][1] = -1e30f;
                if (c0g     > r1g) sacc[ni][2] = -1e30f;
                if (c0g + 1 > r1g) sacc[ni][3] = -1e30f;
            }
        }

        float mx0 = -1e30f, mx1 = -1e30f;
#pragma unroll
        for (int ni = 0; ni < 8; ni++) {
            mx0 = fmaxf(mx0, fmaxf(sacc[ni][0], sacc[ni][1]));
            mx1 = fmaxf(mx1, fmaxf(sacc[ni][2], sacc[ni][3]));
        }
        mx0 = fmaxf(mx0, __shfl_xor_sync(0xffffffffu, mx0, 1));
        mx0 = fmaxf(mx0, __shfl_xor_sync(0xffffffffu, mx0, 2));
        mx1 = fmaxf(mx1, __shfl_xor_sync(0xffffffffu, mx1, 1));
        mx1 = fmaxf(mx1, __shfl_xor_sync(0xffffffffu, mx1, 2));

        const float mn0 = fmaxf(m0, mx0);
        const float mn1 = fmaxf(m1, mx1);
        const float a0 = __expf(m0 - mn0);
        const float a1 = __expf(m1 - mn1);
        m0 = mn0; m1 = mn1;

        float sum0 = 0.f, sum1 = 0.f;
#pragma unroll
        for (int ni = 0; ni < 8; ni++) {
            const float p0 = __expf(sacc[ni][0] - mn0);
            const float p1 = __expf(sacc[ni][1] - mn0);
            const float p2 = __expf(sacc[ni][2] - mn1);
            const float p3 = __expf(sacc[ni][3] - mn1);
            sum0 += p0 + p1;
            sum1 += p2 + p3;
            const int co = ni * 8 + 2 * lc;
            *(uint2*)&Ps[(wr + lr) * QSTR + co]     = make_uint2(f2tf(p0), f2tf(p1));
            *(uint2*)&Ps[(wr + lr + 8) * QSTR + co] = make_uint2(f2tf(p2), f2tf(p3));
        }
        sum0 += __shfl_xor_sync(0xffffffffu, sum0, 1);
        sum0 += __shfl_xor_sync(0xffffffffu, sum0, 2);
        sum1 += __shfl_xor_sync(0xffffffffu, sum1, 1);
        sum1 += __shfl_xor_sync(0xffffffffu, sum1, 2);
        l0 = l0 * a0 + sum0;
        l1 = l1 * a1 + sum1;

#pragma unroll
        for (int ni = 0; ni < 8; ni++) {
            oacc[ni][0] *= a0; oacc[ni][1] *= a0;
            oacc[ni][2] *= a1; oacc[ni][3] *= a1;
        }
        __syncwarp();

#pragma unroll
        for (int ks = 0; ks < 8; ks++) {
            uint32_t af[4];
            const int c = ks * 8 + lc;
            af[0] = Ps[(wr + lr) * QSTR + c];
            af[1] = Ps[(wr + lr + 8) * QSTR + c];
            af[2] = Ps[(wr + lr) * QSTR + c + 4];
            af[3] = Ps[(wr + lr + 8) * QSTR + c + 4];
#pragma unroll
            for (int ni = 0; ni < 8; ni++) {
                uint32_t bf[2];
                const int n = ni * 8 + lr;
                bf[0] = Vs[c * KSTR + n];
                bf[1] = Vs[(c + 4) * KSTR + n];
                mma1688(oacc[ni], af, bf);
            }
        }
    }

    const int b = bh >> 4;
    const int h = bh & 15;
    const float inv0 = 1.f / l0;
    const float inv1 = 1.f / l1;
    const int r0g = q0 + wr + lr;
#pragma unroll
    for (int ni = 0; ni < 8; ni++) {
        const int col = h * DD + ni * 8 + 2 * lc;
        float* d0 = g_a + ((size_t)(b * SS + r0g)) * NXC + col;
        float* d1 = g_a + ((size_t)(b * SS + r0g + 8)) * NXC + col;
        *(uint2*)d0 = make_uint2(f2tf(oacc[ni][0] * inv0),
                                 f2tf(oacc[ni][1] * inv0));
        *(uint2*)d1 = make_uint2(f2tf(oacc[ni][2] * inv1),
                                 f2tf(oacc[ni][3] * inv1));
    }
}

// ---------------------------------------------------------------------------
extern "C" void kernel_launch(void* const* d_in, const int* in_sizes, int n_in,
                              void* d_out, int out_size)
{
    const float* x      = (const float*)d_in[0];
    const float* w_attn = (const float*)d_in[1];
    const float* b_attn = (const float*)d_in[2];
    const float* w_proj = (const float*)d_in[3];
    const float* b_proj = (const float*)d_in[4];
    float* out = (float*)d_out;

    cudaFuncSetAttribute(attn_mma_kernel,
                         cudaFuncAttributeMaxDynamicSharedMemorySize, ATTN_SMEM);

    // 0) Pre-round operands to tf32 in gmem (dst selected inside kernel)
    cvt_tf32_kernel<<<(MTOK * NXC) / 1024, 256>>>(x, 0);
    cvt_tf32_kernel<<<(NXC * 3 * NXC) / 1024, 256>>>(w_attn, 1);
    cvt_tf32_kernel<<<(NXC * NXC) / 1024, 256>>>(w_proj, 2);

    // 1) QKV GEMM (128x64 tiles, 3 CTAs/SM); K written transposed [B,H,D,S]
    tc_gemm<<<dim3(3 * NXC / 64, MTOK / 128), 256>>>(b_attn, nullptr,
                                                     NXC, 3 * NXC, 1);

    // 2) Tensor-core causal flash attention
    attn_mma_kernel<<<dim3(BB * HH, SS / 128), 256, ATTN_SMEM>>>();

    // 3) Projection (128x64 tiles, 3 CTAs/SM)
    tc_gemm<<<dim3(NXC / 64, MTOK / 128), 256>>>(b_proj, out, NXC, NXC, 0);
}